// round 12
// baseline (speedup 1.0000x reference)
#include <cuda_runtime.h>
#include <cstdint>
#include <cstddef>

#define B_ 4
#define T_ 4096
#define H_ 1024
// T_hist = 256 (fixed by setup_inputs)

// Device-global scratch (allocation-free):
__device__ float g_K[(size_t)B_ * T_ * H_];  // tf32-rounded K = h @ W^T
__device__ float g_h[(size_t)B_ * T_ * H_];  // tf32-rounded h (Q and V)
__device__ float g_W[(size_t)H_ * H_];       // tf32-rounded W

__device__ __forceinline__ unsigned f2tf(float f) {
    unsigned u;
    asm("cvt.rna.tf32.f32 %0, %1;" : "=r"(u) : "f"(f));
    return u;
}

__device__ __forceinline__ void mma_tf32(float c[4], const unsigned a[4], const unsigned b[2]) {
    asm volatile(
        "mma.sync.aligned.m16n8k8.row.col.f32.tf32.tf32.f32 "
        "{%0,%1,%2,%3}, {%4,%5,%6,%7}, {%8,%9}, {%0,%1,%2,%3};"
        : "+f"(c[0]), "+f"(c[1]), "+f"(c[2]), "+f"(c[3])
        : "r"(a[0]), "r"(a[1]), "r"(a[2]), "r"(a[3]), "r"(b[0]), "r"(b[1]));
}

__device__ __forceinline__ void cp16(float* dst, const float* src) {
    unsigned d = (unsigned)__cvta_generic_to_shared(dst);
    asm volatile("cp.async.ca.shared.global [%0], [%1], 16;" ::"r"(d), "l"(src));
}
__device__ __forceinline__ void cp_commit() { asm volatile("cp.async.commit_group;"); }
__device__ __forceinline__ void cp_wait0() { asm volatile("cp.async.wait_group 0;"); }

// ============================================================================
// Kernel 0: pre-round h and W to tf32 (bitwise-identical inputs to all mmas)
// ============================================================================
__global__ __launch_bounds__(256)
void preround_kernel(const float* __restrict__ hin, const float* __restrict__ Wm) {
    const size_t NH = (size_t)B_ * T_ * H_ / 4;
    const size_t NW = (size_t)H_ * H_ / 4;
    size_t i = (size_t)blockIdx.x * blockDim.x + threadIdx.x;
    size_t stride = (size_t)gridDim.x * blockDim.x;
    for (size_t p = i; p < NH; p += stride) {
        float4 v = ((const float4*)hin)[p];
        v.x = __uint_as_float(f2tf(v.x));
        v.y = __uint_as_float(f2tf(v.y));
        v.z = __uint_as_float(f2tf(v.z));
        v.w = __uint_as_float(f2tf(v.w));
        ((float4*)g_h)[p] = v;
    }
    for (size_t p = i; p < NW; p += stride) {
        float4 v = ((const float4*)Wm)[p];
        v.x = __uint_as_float(f2tf(v.x));
        v.y = __uint_as_float(f2tf(v.y));
        v.z = __uint_as_float(f2tf(v.z));
        v.w = __uint_as_float(f2tf(v.w));
        ((float4*)g_W)[p] = v;
    }
}

// ============================================================================
// Kernel 1: g_K[m, n] = tf32(sum_k g_h[m, k] * g_W[n, k])
// Block tile 256x128x32, 512 threads (16 warps, 4m x 4n, warp tile 64x32),
// cp.async double-buffered, one barrier per k-iter.
// ============================================================================
#define GBUF 13824  // per-stage floats: A 256x36 (9216) + B 128x36 (4608)
#define GEMM_SMEM_FLOATS (2 * GBUF)  // 110,592 B -> 1 CTA/SM, 16 warps

__global__ __launch_bounds__(512, 1)
void gemm_k_kernel() {
    extern __shared__ float sm[];
    const int m0 = blockIdx.y * 256;
    const int n0 = blockIdx.x * 128;
    const int tid = threadIdx.x;
    const int lane = tid & 31;
    const int warp = tid >> 5;        // 0..15
    const int wm = (warp & 3) * 64;   // 0,64,128,192
    const int wn = (warp >> 2) * 32;  // 0,32,64,96

    float acc[4][4][4];
#pragma unroll
    for (int i = 0; i < 4; i++)
#pragma unroll
        for (int j = 0; j < 4; j++)
#pragma unroll
            for (int k = 0; k < 4; k++) acc[i][j][k] = 0.f;

    auto load_tile = [&](int bi, int kt) {
        float* As = sm + bi * GBUF;     // 256 x 36
        float* Bs = As + 9216;          // 128 x 36
#pragma unroll
        for (int i = 0; i < 4; i++) {   // A: 2048 quads, 4/thread
            int f = tid + i * 512;
            int r = f >> 3;
            int c = (f & 7) * 4;
            cp16(&As[r * 36 + c], &g_h[(size_t)(m0 + r) * H_ + kt + c]);
        }
#pragma unroll
        for (int i = 0; i < 2; i++) {   // B: 1024 quads, 2/thread
            int f = tid + i * 512;
            int r = f >> 3;
            int c = (f & 7) * 4;
            cp16(&Bs[r * 36 + c], &g_W[(size_t)(n0 + r) * H_ + kt + c]);
        }
        cp_commit();
    };

    load_tile(0, 0);
    for (int t = 0; t < 32; t++) {
        cp_wait0();
        __syncthreads();
        if (t + 1 < 32) load_tile((t + 1) & 1, (t + 1) * 32);
        const float* As = sm + (t & 1) * GBUF;
        const float* Bs = As + 9216;
#pragma unroll
        for (int ks = 0; ks < 32; ks += 8) {
            unsigned af[4][4], bf[4][2];
#pragma unroll
            for (int mt = 0; mt < 4; mt++) {
                int r = wm + mt * 16 + (lane >> 2);
                int c = ks + (lane & 3);
                af[mt][0] = __float_as_uint(As[r * 36 + c]);
                af[mt][1] = __float_as_uint(As[(r + 8) * 36 + c]);
                af[mt][2] = __float_as_uint(As[r * 36 + c + 4]);
                af[mt][3] = __float_as_uint(As[(r + 8) * 36 + c + 4]);
            }
#pragma unroll
            for (int nt = 0; nt < 4; nt++) {
                int rn = wn + nt * 8 + (lane >> 2);
                int c = ks + (lane & 3);
                bf[nt][0] = __float_as_uint(Bs[rn * 36 + c]);
                bf[nt][1] = __float_as_uint(Bs[rn * 36 + c + 4]);
            }
#pragma unroll
            for (int mt = 0; mt < 4; mt++)
#pragma unroll
                for (int nt = 0; nt < 4; nt++) mma_tf32(acc[mt][nt], af[mt], bf[nt]);
        }
    }

    // epilogue: store tf32-rounded K (same bits attn phase-1 consumes)
#pragma unroll
    for (int mt = 0; mt < 4; mt++)
#pragma unroll
        for (int nt = 0; nt < 4; nt++) {
            int r = m0 + wm + mt * 16 + (lane >> 2);
            int c = n0 + wn + nt * 8 + (lane & 3) * 2;
            *(float2*)&g_K[(size_t)r * H_ + c] =
                make_float2(__uint_as_float(f2tf(acc[mt][nt][0])),
                            __uint_as_float(f2tf(acc[mt][nt][1])));
            *(float2*)&g_K[(size_t)(r + 8) * H_ + c] =
                make_float2(__uint_as_float(f2tf(acc[mt][nt][2])),
                            __uint_as_float(f2tf(acc[mt][nt][3])));
        }
}

// ============================================================================
// Kernel 2: banded attention (byte-identical to the R10 418.6us win).
// ============================================================================
#define QT 64
#define SP 324  // S row stride: (324m + c)%32 = (4m + c)%32 -> conflict-free

#define P1BUF 13824
#define TILES_FLOATS (2 * P1BUF)
#define ATTN_SMEM_FLOATS (64 * SP + TILES_FLOATS + 64)  // 48448 fl = 193,792 B

__global__ __launch_bounds__(512, 1)
void attn_kernel(float* __restrict__ out) {
    extern __shared__ float smem[];
    float* S = smem;                       // 64 x 324
    float* tiles = smem + 64 * SP;         // TILES_FLOATS
    float* rsum = tiles + TILES_FLOATS;    // 64

    const int b = blockIdx.y;
    const int q0 = blockIdx.x * QT;
    const int kstart = q0 - 256;
    const int tid = threadIdx.x;
    const int lane = tid & 31;
    const int warp = tid >> 5;  // 0..15

    const float* hb = g_h + (size_t)b * T_ * H_;   // pre-rounded Q/V
    const float* Kb = g_K + (size_t)b * T_ * H_;   // pre-rounded K

    // ---------------- Phase 1: S = Q K^T, full 64x320 in one k-sweep --------
    const int wm1 = (warp & 1) * 32;
    const int wn1 = (warp >> 1) * 40;   // 0..280

    {
        float acc[2][5][4];
#pragma unroll
        for (int i = 0; i < 2; i++)
#pragma unroll
            for (int j = 0; j < 5; j++)
#pragma unroll
                for (int k = 0; k < 4; k++) acc[i][j][k] = 0.f;

        auto load1 = [&](int bi, int kt) {
            float* At = tiles + bi * P1BUF;      // 64 x 36
            float* Bt = At + 2304;               // 320 x 36
            {
                int r = tid >> 3;
                int c = (tid & 7) * 4;
                cp16(&At[r * 36 + c], &hb[(size_t)(q0 + r) * H_ + kt + c]);
            }
#pragma unroll
            for (int i = 0; i < 5; i++) {
                int f = tid + i * 512;
                int r = f >> 3;
                int c = (f & 7) * 4;
                int gr = kstart + r;
                gr = gr < 0 ? 0 : gr;  // clamp; masked in softmax
                cp16(&Bt[r * 36 + c], &Kb[(size_t)gr * H_ + kt + c]);
            }
            cp_commit();
        };

        load1(0, 0);
        for (int t = 0; t < 32; t++) {
            cp_wait0();
            __syncthreads();
            if (t + 1 < 32) load1((t + 1) & 1, (t + 1) * 32);
            const float* At = tiles + (t & 1) * P1BUF;
            const float* Bt = At + 2304;
#pragma unroll
            for (int ks = 0; ks < 32; ks += 8) {
                unsigned af[2][4], bf[5][2];
#pragma unroll
                for (int mt = 0; mt < 2; mt++) {
                    int r = wm1 + mt * 16 + (lane >> 2);
                    int c = ks + (lane & 3);
                    af[mt][0] = __float_as_uint(At[r * 36 + c]);
                    af[mt][1] = __float_as_uint(At[(r + 8) * 36 + c]);
                    af[mt][2] = __float_as_uint(At[r * 36 + c + 4]);
                    af[mt][3] = __float_as_uint(At[(r + 8) * 36 + c + 4]);
                }
#pragma unroll
                for (int nt = 0; nt < 5; nt++) {
                    int rn = wn1 + nt * 8 + (lane >> 2);
                    int c = ks + (lane & 3);
                    bf[nt][0] = __float_as_uint(Bt[rn * 36 + c]);
                    bf[nt][1] = __float_as_uint(Bt[rn * 36 + c + 4]);
                }
#pragma unroll
                for (int mt = 0; mt < 2; mt++)
#pragma unroll
                    for (int nt = 0; nt < 5; nt++) mma_tf32(acc[mt][nt], af[mt], bf[nt]);
            }
        }
        __syncthreads();
#pragma unroll
        for (int mt = 0; mt < 2; mt++)
#pragma unroll
            for (int nt = 0; nt < 5; nt++) {
                int r = wm1 + mt * 16 + (lane >> 2);
                int c = wn1 + nt * 8 + (lane & 3) * 2;
                S[r * SP + c] = acc[mt][nt][0];
                S[r * SP + c + 1] = acc[mt][nt][1];
                S[(r + 8) * SP + c] = acc[mt][nt][2];
                S[(r + 8) * SP + c + 1] = acc[mt][nt][3];
            }
    }
    __syncthreads();

    // ---------------- Phase 2: masked softmax (warp per 4 rows) -------------
#pragma unroll
    for (int rr = 0; rr < 4; rr++) {
        int r = warp * 4 + rr;
        int iq = q0 + r;
        float v[10];
        float mx = -1e30f;
#pragma unroll
        for (int cc = 0; cc < 10; cc++) {
            int c = lane + cc * 32;
            int j = kstart + c;
            bool valid = (j >= 0) && (j <= iq) && (j >= iq - 255);
            v[cc] = valid ? S[r * SP + c] * 0.03125f : -1e30f;
            mx = fmaxf(mx, v[cc]);
        }
#pragma unroll
        for (int o = 16; o > 0; o >>= 1) mx = fmaxf(mx, __shfl_xor_sync(0xffffffffu, mx, o));
        float sum = 0.f;
#pragma unroll
        for (int cc = 0; cc < 10; cc++) {
            int c = lane + cc * 32;
            float p = (v[cc] > -1e29f) ? __expf(v[cc] - mx) : 0.f;
            sum += p;
            S[r * SP + c] = __uint_as_float(f2tf(p));
        }
#pragma unroll
        for (int o = 16; o > 0; o >>= 1) sum += __shfl_xor_sync(0xffffffffu, sum, o);
        if (lane == 0) rsum[r] = 1.0f / sum;
    }
    __syncthreads();

    // ---------------- Phase 3: O = P V, 64x256 per round (4 rounds) ---------
    const int wm3 = (warp & 1) * 32;
    const int wn3 = (warp >> 1) * 32;
    const int t0 = (kstart < 0) ? ((-kstart) >> 5) : 0;

    for (int hc = 0; hc < 4; hc++) {
        float acc[2][4][4];
#pragma unroll
        for (int i = 0; i < 2; i++)
#pragma unroll
            for (int j = 0; j < 4; j++)
#pragma unroll
                for (int k = 0; k < 4; k++) acc[i][j][k] = 0.f;

        auto load3 = [&](int bi, int tt) {
            float* Vt = tiles + bi * 8448;  // 32 x 264 [k][n]
#pragma unroll
            for (int i = 0; i < 4; i++) {
                int f = tid + i * 512;
                int k = f >> 6;
                int n4 = (f & 63) * 4;
                int gr = kstart + tt * 32 + k;
                gr = gr < 0 ? 0 : gr;
                cp16(&Vt[k * 264 + n4], &hb[(size_t)gr * H_ + hc * 256 + n4]);
            }
            cp_commit();
        };

        load3(t0 & 1, t0);
        for (int t = t0; t < 10; t++) {
            cp_wait0();
            __syncthreads();
            if (t + 1 < 10) load3((t + 1) & 1, t + 1);
            const float* Vt = tiles + (t & 1) * 8448;
            int kt = t * 32;
#pragma unroll
            for (int ks = 0; ks < 32; ks += 8) {
                unsigned af[2][4], bf[4][2];
#pragma unroll
                for (int mt = 0; mt < 2; mt++) {
                    int r = wm3 + mt * 16 + (lane >> 2);
                    int c = kt + ks + (lane & 3);
                    af[mt][0] = __float_as_uint(S[r * SP + c]);
                    af[mt][1] = __float_as_uint(S[(r + 8) * SP + c]);
                    af[mt][2] = __float_as_uint(S[r * SP + c + 4]);
                    af[mt][3] = __float_as_uint(S[(r + 8) * SP + c + 4]);
                }
#pragma unroll
                for (int nt = 0; nt < 4; nt++) {
                    int kk = ks + (lane & 3);
                    int n = wn3 + nt * 8 + (lane >> 2);
                    bf[nt][0] = __float_as_uint(Vt[kk * 264 + n]);
                    bf[nt][1] = __float_as_uint(Vt[(kk + 4) * 264 + n]);
                }
#pragma unroll
                for (int mt = 0; mt < 2; mt++)
#pragma unroll
                    for (int nt = 0; nt < 4; nt++) mma_tf32(acc[mt][nt], af[mt], bf[nt]);
            }
        }
        __syncthreads();
#pragma unroll
        for (int mt = 0; mt < 2; mt++) {
            int r = wm3 + mt * 16 + (lane >> 2);
            float s0 = rsum[r];
            float s1 = rsum[r + 8];
#pragma unroll
            for (int nt = 0; nt < 4; nt++) {
                int c = hc * 256 + wn3 + nt * 8 + (lane & 3) * 2;
                size_t o0 = ((size_t)b * T_ + q0 + r) * H_ + c;
                *(float2*)&out[o0] = make_float2(acc[mt][nt][0] * s0, acc[mt][nt][1] * s0);
                *(float2*)&out[o0 + (size_t)8 * H_] =
                    make_float2(acc[mt][nt][2] * s1, acc[mt][nt][3] * s1);
            }
        }
    }
}

// ============================================================================
extern "C" void kernel_launch(void* const* d_in, const int* in_sizes, int n_in,
                              void* d_out, int out_size) {
    const float* h = (const float*)d_in[0];
    const float* W = (const float*)d_in[1];
    // d_in[2] = T_hist (always 256)
    float* out = (float*)d_out;

    preround_kernel<<<2048, 256>>>(h, W);

    cudaFuncSetAttribute(gemm_k_kernel, cudaFuncAttributeMaxDynamicSharedMemorySize,
                         GEMM_SMEM_FLOATS * 4);
    gemm_k_kernel<<<dim3(8, 64), 512, GEMM_SMEM_FLOATS * 4>>>();

    cudaFuncSetAttribute(attn_kernel, cudaFuncAttributeMaxDynamicSharedMemorySize,
                         ATTN_SMEM_FLOATS * 4);
    attn_kernel<<<dim3(T_ / QT, B_), 512, ATTN_SMEM_FLOATS * 4>>>(out);
}

// round 13
// speedup vs baseline: 1.0071x; 1.0071x over previous
#include <cuda_runtime.h>
#include <cstdint>
#include <cstddef>

#define B_ 4
#define T_ 4096
#define H_ 1024
// T_hist = 256 (fixed by setup_inputs)

// Device-global scratch (allocation-free):
__device__ float g_K[(size_t)B_ * T_ * H_];  // tf32-rounded K = h @ W^T
__device__ float g_h[(size_t)B_ * T_ * H_];  // tf32-rounded h (Q and V)
__device__ float g_W[(size_t)H_ * H_];       // tf32-rounded W

__device__ __forceinline__ unsigned f2tf(float f) {
    unsigned u;
    asm("cvt.rna.tf32.f32 %0, %1;" : "=r"(u) : "f"(f));
    return u;
}

__device__ __forceinline__ void mma_tf32(float c[4], const unsigned a[4], const unsigned b[2]) {
    asm volatile(
        "mma.sync.aligned.m16n8k8.row.col.f32.tf32.tf32.f32 "
        "{%0,%1,%2,%3}, {%4,%5,%6,%7}, {%8,%9}, {%0,%1,%2,%3};"
        : "+f"(c[0]), "+f"(c[1]), "+f"(c[2]), "+f"(c[3])
        : "r"(a[0]), "r"(a[1]), "r"(a[2]), "r"(a[3]), "r"(b[0]), "r"(b[1]));
}

__device__ __forceinline__ void cp16(float* dst, const float* src) {
    unsigned d = (unsigned)__cvta_generic_to_shared(dst);
    asm volatile("cp.async.ca.shared.global [%0], [%1], 16;" ::"r"(d), "l"(src));
}
__device__ __forceinline__ void cp_commit() { asm volatile("cp.async.commit_group;"); }
__device__ __forceinline__ void cp_wait0() { asm volatile("cp.async.wait_group 0;"); }

// ============================================================================
// Kernel 0: pre-round h and W to tf32 (bitwise-identical inputs to all mmas)
// ============================================================================
__global__ __launch_bounds__(256)
void preround_kernel(const float* __restrict__ hin, const float* __restrict__ Wm) {
    const size_t NH = (size_t)B_ * T_ * H_ / 4;
    const size_t NW = (size_t)H_ * H_ / 4;
    size_t i = (size_t)blockIdx.x * blockDim.x + threadIdx.x;
    size_t stride = (size_t)gridDim.x * blockDim.x;
    for (size_t p = i; p < NH; p += stride) {
        float4 v = ((const float4*)hin)[p];
        v.x = __uint_as_float(f2tf(v.x));
        v.y = __uint_as_float(f2tf(v.y));
        v.z = __uint_as_float(f2tf(v.z));
        v.w = __uint_as_float(f2tf(v.w));
        ((float4*)g_h)[p] = v;
    }
    for (size_t p = i; p < NW; p += stride) {
        float4 v = ((const float4*)Wm)[p];
        v.x = __uint_as_float(f2tf(v.x));
        v.y = __uint_as_float(f2tf(v.y));
        v.z = __uint_as_float(f2tf(v.z));
        v.w = __uint_as_float(f2tf(v.w));
        ((float4*)g_W)[p] = v;
    }
}

// ============================================================================
// Kernel 1: g_K[m, n] = tf32(sum_k g_h[m, k] * g_W[n, k])
// Block tile 128x128x32, 8 warps (2m x 4n), cp.async double-buffered,
// 2 CTAs/SM (R10 measured-best config).
// ============================================================================
#define GEMM_SMEM_FLOATS (4 * 128 * 36)  // As[2] + Bs[2], 73728 B

__global__ __launch_bounds__(256, 2)
void gemm_k_kernel() {
    extern __shared__ float sm[];
    const int m0 = blockIdx.y * 128;
    const int n0 = blockIdx.x * 128;
    const int tid = threadIdx.x;
    const int lane = tid & 31;
    const int warp = tid >> 5;
    const int wm = (warp & 1) * 64;
    const int wn = (warp >> 1) * 32;

    float acc[4][4][4];
#pragma unroll
    for (int i = 0; i < 4; i++)
#pragma unroll
        for (int j = 0; j < 4; j++)
#pragma unroll
            for (int k = 0; k < 4; k++) acc[i][j][k] = 0.f;

    auto load_tile = [&](int bi, int kt) {
        float* As = sm + bi * 4608;
        float* Bs = sm + 9216 + bi * 4608;
#pragma unroll
        for (int i = 0; i < 4; i++) {
            int f = tid + i * 256;  // 1024 float4 slots: 128 rows x 8 quads
            int r = f >> 3;
            int c = (f & 7) * 4;
            cp16(&As[r * 36 + c], &g_h[(size_t)(m0 + r) * H_ + kt + c]);
            cp16(&Bs[r * 36 + c], &g_W[(size_t)(n0 + r) * H_ + kt + c]);
        }
        cp_commit();
    };

    load_tile(0, 0);
    for (int t = 0; t < 32; t++) {
        cp_wait0();
        __syncthreads();
        if (t + 1 < 32) load_tile((t + 1) & 1, (t + 1) * 32);
        const float* As = sm + (t & 1) * 4608;
        const float* Bs = sm + 9216 + (t & 1) * 4608;
#pragma unroll
        for (int ks = 0; ks < 32; ks += 8) {
            unsigned af[4][4], bf[4][2];
#pragma unroll
            for (int mt = 0; mt < 4; mt++) {
                int r = wm + mt * 16 + (lane >> 2);
                int c = ks + (lane & 3);
                af[mt][0] = __float_as_uint(As[r * 36 + c]);
                af[mt][1] = __float_as_uint(As[(r + 8) * 36 + c]);
                af[mt][2] = __float_as_uint(As[r * 36 + c + 4]);
                af[mt][3] = __float_as_uint(As[(r + 8) * 36 + c + 4]);
            }
#pragma unroll
            for (int nt = 0; nt < 4; nt++) {
                int rn = wn + nt * 8 + (lane >> 2);
                int c = ks + (lane & 3);
                bf[nt][0] = __float_as_uint(Bs[rn * 36 + c]);
                bf[nt][1] = __float_as_uint(Bs[rn * 36 + c + 4]);
            }
#pragma unroll
            for (int mt = 0; mt < 4; mt++)
#pragma unroll
                for (int nt = 0; nt < 4; nt++) mma_tf32(acc[mt][nt], af[mt], bf[nt]);
        }
    }

    // epilogue: store tf32-rounded K (same bits attn phase-1 consumes)
#pragma unroll
    for (int mt = 0; mt < 4; mt++)
#pragma unroll
        for (int nt = 0; nt < 4; nt++) {
            int r = m0 + wm + mt * 16 + (lane >> 2);
            int c = n0 + wn + nt * 8 + (lane & 3) * 2;
            *(float2*)&g_K[(size_t)r * H_ + c] =
                make_float2(__uint_as_float(f2tf(acc[mt][nt][0])),
                            __uint_as_float(f2tf(acc[mt][nt][1])));
            *(float2*)&g_K[(size_t)(r + 8) * H_ + c] =
                make_float2(__uint_as_float(f2tf(acc[mt][nt][2])),
                            __uint_as_float(f2tf(acc[mt][nt][3])));
        }
}

// ============================================================================
// Kernel 2: banded attention. 512 threads (16 warps), one block per
// (b, 64-query tile). Band: keys j in [q0-256, q0+63] -> 320 cols.
// Phase 1: full 64x320 S in ONE k-sweep (R10). 16 warps 2m x 8n, tile 32x40.
// Phase 3: 64x512 per round (2 rounds). 16 warps 2m x 8n, warp tile 32x64 —
//          S fragments re-read half as often, barriers halved.
// Smem 216.3 KB -> 1 CTA/SM, 16 warps/SM.
// ============================================================================
#define QT 64
#define SP 324  // S row stride: (324m + c)%32 = (4m + c)%32 -> conflict-free

#define P1BUF 13824            // phase1 per-stage: At 64x36 + Bt 320x36
#define P3BUF 16640            // phase3 per-stage: Vt 32x520
#define TILES_FLOATS (2 * P3BUF)  // 33280 fl (phase1 2x13824=27648 fits)
#define ATTN_SMEM_FLOATS (64 * SP + TILES_FLOATS + 64)  // 54080 fl = 216,320 B

__global__ __launch_bounds__(512, 1)
void attn_kernel(float* __restrict__ out) {
    extern __shared__ float smem[];
    float* S = smem;                       // 64 x 324
    float* tiles = smem + 64 * SP;         // TILES_FLOATS
    float* rsum = tiles + TILES_FLOATS;    // 64

    const int b = blockIdx.y;
    const int q0 = blockIdx.x * QT;
    const int kstart = q0 - 256;
    const int tid = threadIdx.x;
    const int lane = tid & 31;
    const int warp = tid >> 5;  // 0..15

    const float* hb = g_h + (size_t)b * T_ * H_;   // pre-rounded Q/V
    const float* Kb = g_K + (size_t)b * T_ * H_;   // pre-rounded K

    // ---------------- Phase 1: S = Q K^T, full 64x320 in one k-sweep --------
    const int wm1 = (warp & 1) * 32;
    const int wn1 = (warp >> 1) * 40;   // 0..280

    {
        float acc[2][5][4];
#pragma unroll
        for (int i = 0; i < 2; i++)
#pragma unroll
            for (int j = 0; j < 5; j++)
#pragma unroll
                for (int k = 0; k < 4; k++) acc[i][j][k] = 0.f;

        auto load1 = [&](int bi, int kt) {
            float* At = tiles + bi * P1BUF;      // 64 x 36
            float* Bt = At + 2304;               // 320 x 36
            {
                int r = tid >> 3;
                int c = (tid & 7) * 4;
                cp16(&At[r * 36 + c], &hb[(size_t)(q0 + r) * H_ + kt + c]);
            }
#pragma unroll
            for (int i = 0; i < 5; i++) {
                int f = tid + i * 512;
                int r = f >> 3;
                int c = (f & 7) * 4;
                int gr = kstart + r;
                gr = gr < 0 ? 0 : gr;  // clamp; masked in softmax
                cp16(&Bt[r * 36 + c], &Kb[(size_t)gr * H_ + kt + c]);
            }
            cp_commit();
        };

        load1(0, 0);
        for (int t = 0; t < 32; t++) {
            cp_wait0();
            __syncthreads();
            if (t + 1 < 32) load1((t + 1) & 1, (t + 1) * 32);
            const float* At = tiles + (t & 1) * P1BUF;
            const float* Bt = At + 2304;
#pragma unroll
            for (int ks = 0; ks < 32; ks += 8) {
                unsigned af[2][4], bf[5][2];
#pragma unroll
                for (int mt = 0; mt < 2; mt++) {
                    int r = wm1 + mt * 16 + (lane >> 2);
                    int c = ks + (lane & 3);
                    af[mt][0] = __float_as_uint(At[r * 36 + c]);
                    af[mt][1] = __float_as_uint(At[(r + 8) * 36 + c]);
                    af[mt][2] = __float_as_uint(At[r * 36 + c + 4]);
                    af[mt][3] = __float_as_uint(At[(r + 8) * 36 + c + 4]);
                }
#pragma unroll
                for (int nt = 0; nt < 5; nt++) {
                    int rn = wn1 + nt * 8 + (lane >> 2);
                    int c = ks + (lane & 3);
                    bf[nt][0] = __float_as_uint(Bt[rn * 36 + c]);
                    bf[nt][1] = __float_as_uint(Bt[rn * 36 + c + 4]);
                }
#pragma unroll
                for (int mt = 0; mt < 2; mt++)
#pragma unroll
                    for (int nt = 0; nt < 5; nt++) mma_tf32(acc[mt][nt], af[mt], bf[nt]);
            }
        }
        __syncthreads();
#pragma unroll
        for (int mt = 0; mt < 2; mt++)
#pragma unroll
            for (int nt = 0; nt < 5; nt++) {
                int r = wm1 + mt * 16 + (lane >> 2);
                int c = wn1 + nt * 8 + (lane & 3) * 2;
                S[r * SP + c] = acc[mt][nt][0];
                S[r * SP + c + 1] = acc[mt][nt][1];
                S[(r + 8) * SP + c] = acc[mt][nt][2];
                S[(r + 8) * SP + c + 1] = acc[mt][nt][3];
            }
    }
    __syncthreads();

    // ---------------- Phase 2: masked softmax (warp per 4 rows) -------------
#pragma unroll
    for (int rr = 0; rr < 4; rr++) {
        int r = warp * 4 + rr;
        int iq = q0 + r;
        float v[10];
        float mx = -1e30f;
#pragma unroll
        for (int cc = 0; cc < 10; cc++) {
            int c = lane + cc * 32;
            int j = kstart + c;
            bool valid = (j >= 0) && (j <= iq) && (j >= iq - 255);
            v[cc] = valid ? S[r * SP + c] * 0.03125f : -1e30f;
            mx = fmaxf(mx, v[cc]);
        }
#pragma unroll
        for (int o = 16; o > 0; o >>= 1) mx = fmaxf(mx, __shfl_xor_sync(0xffffffffu, mx, o));
        float sum = 0.f;
#pragma unroll
        for (int cc = 0; cc < 10; cc++) {
            int c = lane + cc * 32;
            float p = (v[cc] > -1e29f) ? __expf(v[cc] - mx) : 0.f;
            sum += p;
            S[r * SP + c] = __uint_as_float(f2tf(p));
        }
#pragma unroll
        for (int o = 16; o > 0; o >>= 1) sum += __shfl_xor_sync(0xffffffffu, sum, o);
        if (lane == 0) rsum[r] = 1.0f / sum;
    }
    __syncthreads();

    // ---------------- Phase 3: O = P V, 64x512 per round (2 rounds) ---------
    // 16 warps: 2m x 8n, warp tile 32x64 (8 mma n-tiles)
    const int wm3 = (warp & 1) * 32;
    const int wn3 = (warp >> 1) * 64;   // 0..448
    const int t0 = (kstart < 0) ? ((-kstart) >> 5) : 0;

    for (int hc = 0; hc < 2; hc++) {  // 512 cols per round
        float acc[2][8][4];
#pragma unroll
        for (int i = 0; i < 2; i++)
#pragma unroll
            for (int j = 0; j < 8; j++)
#pragma unroll
                for (int k = 0; k < 4; k++) acc[i][j][k] = 0.f;

        auto load3 = [&](int bi, int tt) {
            float* Vt = tiles + bi * P3BUF;  // 32 x 520 [k][n]
#pragma unroll
            for (int i = 0; i < 8; i++) {
                int f = tid + i * 512;  // 4096 slots: 32 k-rows x 128 quads
                int k = f >> 7;
                int n4 = (f & 127) * 4;
                int gr = kstart + tt * 32 + k;
                gr = gr < 0 ? 0 : gr;  // P is 0 there
                cp16(&Vt[k * 520 + n4], &hb[(size_t)gr * H_ + hc * 512 + n4]);
            }
            cp_commit();
        };

        load3(t0 & 1, t0);
        for (int t = t0; t < 10; t++) {
            cp_wait0();
            __syncthreads();
            if (t + 1 < 10) load3((t + 1) & 1, t + 1);
            const float* Vt = tiles + (t & 1) * P3BUF;
            int kt = t * 32;
#pragma unroll
            for (int ks = 0; ks < 32; ks += 8) {
                unsigned af[2][4], bf[8][2];
#pragma unroll
                for (int mt = 0; mt < 2; mt++) {
                    int r = wm3 + mt * 16 + (lane >> 2);
                    int c = kt + ks + (lane & 3);
                    af[mt][0] = __float_as_uint(S[r * SP + c]);
                    af[mt][1] = __float_as_uint(S[(r + 8) * SP + c]);
                    af[mt][2] = __float_as_uint(S[r * SP + c + 4]);
                    af[mt][3] = __float_as_uint(S[(r + 8) * SP + c + 4]);
                }
#pragma unroll
                for (int nt = 0; nt < 8; nt++) {
                    int kk = ks + (lane & 3);
                    int n = wn3 + nt * 8 + (lane >> 2);
                    bf[nt][0] = __float_as_uint(Vt[kk * 520 + n]);
                    bf[nt][1] = __float_as_uint(Vt[(kk + 4) * 520 + n]);
                }
#pragma unroll
                for (int mt = 0; mt < 2; mt++)
#pragma unroll
                    for (int nt = 0; nt < 8; nt++) mma_tf32(acc[mt][nt], af[mt], bf[nt]);
            }
        }
        __syncthreads();  // last compute done before next hc's preload overwrites
        // epilogue: normalize and store
#pragma unroll
        for (int mt = 0; mt < 2; mt++) {
            int r = wm3 + mt * 16 + (lane >> 2);
            float s0 = rsum[r];
            float s1 = rsum[r + 8];
#pragma unroll
            for (int nt = 0; nt < 8; nt++) {
                int c = hc * 512 + wn3 + nt * 8 + (lane & 3) * 2;
                size_t o0 = ((size_t)b * T_ + q0 + r) * H_ + c;
                *(float2*)&out[o0] = make_float2(acc[mt][nt][0] * s0, acc[mt][nt][1] * s0);
                *(float2*)&out[o0 + (size_t)8 * H_] =
                    make_float2(acc[mt][nt][2] * s1, acc[mt][nt][3] * s1);
            }
        }
    }
}

// ============================================================================
extern "C" void kernel_launch(void* const* d_in, const int* in_sizes, int n_in,
                              void* d_out, int out_size) {
    const float* h = (const float*)d_in[0];
    const float* W = (const float*)d_in[1];
    // d_in[2] = T_hist (always 256)
    float* out = (float*)d_out;

    preround_kernel<<<2048, 256>>>(h, W);

    cudaFuncSetAttribute(gemm_k_kernel, cudaFuncAttributeMaxDynamicSharedMemorySize,
                         GEMM_SMEM_FLOATS * 4);
    gemm_k_kernel<<<dim3(8, 128), 256, GEMM_SMEM_FLOATS * 4>>>();

    cudaFuncSetAttribute(attn_kernel, cudaFuncAttributeMaxDynamicSharedMemorySize,
                         ATTN_SMEM_FLOATS * 4);
    attn_kernel<<<dim3(T_ / QT, B_), 512, ATTN_SMEM_FLOATS * 4>>>(out);
}